// round 3
// baseline (speedup 1.0000x reference)
#include <cuda_runtime.h>

// Analytic collapse of the QNN circuit:
//   z_i   = cos(x_i + theta_i)
//   out_w = prod_{i=0..w} z_i        (w = 1..9)
//   out_0 = prod_{i=1..9} z_i
//
// 2 rows per thread: 80 B = 5 aligned float4 -> all traffic is LDG.128/STG.128,
// MLP=5 front-batched, whole input in flight in one DRAM round trip.

#define NQ   10
#define TPB  256
#define RPT  2                       // rows per thread

__device__ __forceinline__ void row_products(const float* __restrict__ xr,
                                             const float* __restrict__ th,
                                             float* __restrict__ r)
{
    float z[NQ];
#pragma unroll
    for (int i = 0; i < NQ; i++) z[i] = __cosf(xr[i] + th[i]);

    float p23 = z[2] * z[3];
    float p45 = z[4] * z[5];
    float p67 = z[6] * z[7];
    float p89 = z[8] * z[9];

    r[1] = z[0] * z[1];
    r[2] = r[1] * z[2];
    r[3] = r[1] * p23;
    r[4] = r[3] * z[4];
    r[5] = r[3] * p45;
    r[6] = r[5] * z[6];
    r[7] = r[5] * p67;
    r[8] = r[7] * z[8];
    r[9] = r[7] * p89;
    // out0 = z1..z9
    float q = z[1] * p23;
    q = q * p45;
    q = q * p67;
    r[0] = q * p89;
}

__global__ __launch_bounds__(TPB) void qnn_expz_kernel(
    const float4* __restrict__ x4,
    const float*  __restrict__ theta,
    float4* __restrict__ o4)
{
    const int t    = blockIdx.x * TPB + threadIdx.x;
    const long long v = (long long)t * 5;    // 5 float4 = 2 rows = 20 floats

    // Front-batched MLP=5 LDG.128 burst.
    float4 a0 = x4[v + 0];
    float4 a1 = x4[v + 1];
    float4 a2 = x4[v + 2];
    float4 a3 = x4[v + 3];
    float4 a4 = x4[v + 4];

    float th[NQ];
#pragma unroll
    for (int i = 0; i < NQ; i++) th[i] = __ldg(theta + i);

    float in[2 * NQ] = {
        a0.x, a0.y, a0.z, a0.w, a1.x, a1.y, a1.z, a1.w, a2.x, a2.y,
        a2.z, a2.w, a3.x, a3.y, a3.z, a3.w, a4.x, a4.y, a4.z, a4.w
    };

    float r[2 * NQ];
    row_products(in,      th, r);
    row_products(in + NQ, th, r + NQ);

    o4[v + 0] = make_float4(r[0],  r[1],  r[2],  r[3]);
    o4[v + 1] = make_float4(r[4],  r[5],  r[6],  r[7]);
    o4[v + 2] = make_float4(r[8],  r[9],  r[10], r[11]);
    o4[v + 3] = make_float4(r[12], r[13], r[14], r[15]);
    o4[v + 4] = make_float4(r[16], r[17], r[18], r[19]);
}

extern "C" void kernel_launch(void* const* d_in, const int* in_sizes, int n_in,
                              void* d_out, int out_size)
{
    const float* x     = (const float*)d_in[0];   // (65536, 10) f32
    const float* theta = (const float*)d_in[1];   // (10,) f32
    float* out         = (float*)d_out;           // (65536, 10) f32

    const int batch  = in_sizes[0] / NQ;          // 65536
    const int blocks = batch / (TPB * RPT);       // 128

    qnn_expz_kernel<<<blocks, TPB>>>(
        reinterpret_cast<const float4*>(x), theta,
        reinterpret_cast<float4*>(out));
}